// round 2
// baseline (speedup 1.0000x reference)
#include <cuda_runtime.h>
#include <stdint.h>

// GraphPoolOut: voxel max-pool
//   vertices: [N=1e6, 3] int32 (JAX silently downcasts int64->int32), values in [0,256)
//   features: [N, 64] float32
//   out: [64^3 * 64] float32 ; empty voxels -> 0
//
// Plan: order-preserving u32 key transform + return-less atomicMax (REDG.MAX.U32),
// warp-per-point coalesced feature loads, in-place decode pass.

#define GP_GRID   64
#define GP_NVOX   (GP_GRID * GP_GRID * GP_GRID)   // 262144
#define GP_C      64

// ---- order-preserving float <-> u32 key ----------------------------------
// key(f) is monotone in f over all non-NaN floats; key(-inf)=0x007FFFFF > 0,
// so 0 is a safe "empty" sentinel.
__device__ __forceinline__ unsigned int f2key(float f) {
    unsigned int b = __float_as_uint(f);
    return b ^ ((b & 0x80000000u) ? 0xFFFFFFFFu : 0x80000000u);
}
__device__ __forceinline__ float key2f(unsigned int k) {
    unsigned int b = (k & 0x80000000u) ? (k ^ 0x80000000u) : ~k;
    return __uint_as_float(b);
}

// ---- kernel 1: zero the key buffer (d_out reused as u32 keys) -------------
__global__ void gp_init_kernel(uint4* __restrict__ out, int n4) {
    int i = blockIdx.x * blockDim.x + threadIdx.x;
    if (i < n4) {
        uint4 z; z.x = 0u; z.y = 0u; z.z = 0u; z.w = 0u;
        out[i] = z;
    }
}

// ---- kernel 2: warp-per-point scatter max ---------------------------------
__global__ void gp_pool_kernel(const int* __restrict__ verts,
                               const float2*   __restrict__ feats,
                               unsigned int*   __restrict__ out,
                               int n_pts) {
    int gwarp = (int)((blockIdx.x * (long long)blockDim.x + threadIdx.x) >> 5);
    int lane  = threadIdx.x & 31;
    if (gwarp >= n_pts) return;

    int vox = 0;
    if (lane == 0) {
        // coords are nonneg < 256; >>2 == //4
        int v0 = verts[(size_t)gwarp * 3 + 0] >> 2;
        int v1 = verts[(size_t)gwarp * 3 + 1] >> 2;
        int v2 = verts[(size_t)gwarp * 3 + 2] >> 2;
        vox = v0 * (GP_GRID * GP_GRID) + v1 * GP_GRID + v2;
    }
    vox = __shfl_sync(0xFFFFFFFFu, vox, 0);

    // coalesced 256B read: lane covers channels 2*lane, 2*lane+1
    float2 f = feats[(size_t)gwarp * 32 + lane];

    unsigned int* base = out + (size_t)vox * GP_C;
    // return value unused -> ptxas emits RED (no round-trip)
    atomicMax(base + 2 * lane,     f2key(f.x));
    atomicMax(base + 2 * lane + 1, f2key(f.y));
}

// ---- kernel 3: in-place key -> float decode -------------------------------
__global__ void gp_decode_kernel(uint4* __restrict__ data, int n4) {
    int i = blockIdx.x * blockDim.x + threadIdx.x;
    if (i < n4) {
        uint4 k = data[i];
        float4 o;
        o.x = (k.x == 0u) ? 0.0f : key2f(k.x);
        o.y = (k.y == 0u) ? 0.0f : key2f(k.y);
        o.z = (k.z == 0u) ? 0.0f : key2f(k.z);
        o.w = (k.w == 0u) ? 0.0f : key2f(k.w);
        *reinterpret_cast<float4*>(&data[i]) = *reinterpret_cast<float4*>(&o);
    }
}

extern "C" void kernel_launch(void* const* d_in, const int* in_sizes, int n_in,
                              void* d_out, int out_size) {
    const int*    verts = (const int*)d_in[0];            // [N,3] int32
    const float2* feats = (const float2*)d_in[1];         // [N,64] f32 as [N,32] f2
    unsigned int* outk  = (unsigned int*)d_out;           // [NVOX*64] keys -> floats

    int n_pts = in_sizes[0] / 3;                          // 1,000,000
    int n_out = out_size;                                 // NVOX * 64 = 16,777,216
    int n4    = n_out / 4;                                // 4,194,304

    const int T = 256;

    // 1) zero keys
    gp_init_kernel<<<(n4 + T - 1) / T, T>>>((uint4*)outk, n4);

    // 2) scatter-max: warp per point
    long long total_threads = (long long)n_pts * 32;
    int blocks = (int)((total_threads + T - 1) / T);
    gp_pool_kernel<<<blocks, T>>>(verts, feats, outk, n_pts);

    // 3) decode keys to floats in place
    gp_decode_kernel<<<(n4 + T - 1) / T, T>>>((uint4*)outk, n4);
}

// round 3
// speedup vs baseline: 1.0057x; 1.0057x over previous
#include <cuda_runtime.h>
#include <stdint.h>
#include <math_constants.h>

// GraphPoolOut: voxel max-pool (bucket + gather formulation)
//   vertices: [N=1e6, 3] int32, values in [0,256)
//   features: [N, 64] float32
//   out: [64^3, 64] float32 flat; empty voxels -> 0
//
// R2 showed the 64M scalar atomicMax REDs bound the old scatter kernel
// (~105us). This version builds per-voxel point lists with 1M cheap
// atomicAdds, then gathers with plain loads: no init, no decode.

#define GP_GRID   64
#define GP_NVOX   (GP_GRID * GP_GRID * GP_GRID)   // 262144
#define GP_C      64
#define GP_CAP    32   // max points per voxel (Poisson(3.81): P(>31) ~ 1e-12)

// scratch (static device memory; no allocation APIs)
__device__ unsigned int g_cnt[GP_NVOX];            // 1 MB
__device__ int          g_bucket[GP_NVOX * GP_CAP]; // 32 MB

// ---- kernel 0: zero counters ----------------------------------------------
__global__ void gp_zero_cnt(void) {
    int i = blockIdx.x * blockDim.x + threadIdx.x;
    uint4 z; z.x = 0u; z.y = 0u; z.z = 0u; z.w = 0u;
    reinterpret_cast<uint4*>(g_cnt)[i] = z;        // NVOX/4 = 65536 threads exact
}

// ---- kernel 1: build per-voxel buckets ------------------------------------
__global__ void gp_build(const int* __restrict__ verts, int n_pts) {
    int i = blockIdx.x * blockDim.x + threadIdx.x;
    if (i >= n_pts) return;
    int v0 = verts[3 * i + 0] >> 2;                // coords in [0,256): >>2 == //4
    int v1 = verts[3 * i + 1] >> 2;
    int v2 = verts[3 * i + 2] >> 2;
    int vox = (v0 << 12) | (v1 << 6) | v2;
    unsigned int pos = atomicAdd(&g_cnt[vox], 1u);
    if (pos < GP_CAP)
        g_bucket[(size_t)vox * GP_CAP + pos] = i;
}

// ---- kernel 2: warp-per-voxel gather max ----------------------------------
__global__ void gp_gather(const float2* __restrict__ feats,
                          float2*       __restrict__ out) {
    int vox  = (int)((blockIdx.x * (long long)blockDim.x + threadIdx.x) >> 5);
    int lane = threadIdx.x & 31;
    if (vox >= GP_NVOX) return;

    unsigned int cnt = g_cnt[vox];                 // broadcast load
    if (cnt > GP_CAP) cnt = GP_CAP;

    // one coalesced 128B load pulls all bucket entries into lanes
    int myidx = 0;
    if (lane < (int)cnt)
        myidx = g_bucket[(size_t)vox * GP_CAP + lane];

    float2 acc;
    acc.x = -CUDART_INF_F;
    acc.y = -CUDART_INF_F;

    for (int j = 0; j < (int)cnt; ++j) {
        int p = __shfl_sync(0xFFFFFFFFu, myidx, j);
        float2 f = feats[(size_t)p * 32 + lane];   // coalesced 256B per point
        acc.x = fmaxf(acc.x, f.x);
        acc.y = fmaxf(acc.y, f.y);
    }

    if (cnt == 0) { acc.x = 0.0f; acc.y = 0.0f; }  // empty voxel -> zeros
    out[(size_t)vox * 32 + lane] = acc;            // coalesced 256B per voxel
}

extern "C" void kernel_launch(void* const* d_in, const int* in_sizes, int n_in,
                              void* d_out, int out_size) {
    const int*    verts = (const int*)d_in[0];     // [N,3] int32
    const float2* feats = (const float2*)d_in[1];  // [N,64] f32 viewed as [N,32] f2
    float2*       out   = (float2*)d_out;          // [NVOX*64] f32 viewed as f2

    int n_pts = in_sizes[0] / 3;                   // 1,000,000

    const int T = 256;

    // 0) zero counters: NVOX/4 uint4 = 65536 threads
    gp_zero_cnt<<<(GP_NVOX / 4) / T, T>>>();

    // 1) build buckets: thread per point
    gp_build<<<(n_pts + T - 1) / T, T>>>(verts, n_pts);

    // 2) gather: warp per voxel
    long long total_threads = (long long)GP_NVOX * 32;
    gp_gather<<<(int)((total_threads + T - 1) / T), T>>>(feats, out);
}